// round 10
// baseline (speedup 1.0000x reference)
#include <cuda_runtime.h>
#include <math.h>

// Sinkhorn approximate EMD: B=8, N=2048, 3D points, 50 iterations.
// R10: two batches per CTA with INTERLEAVED barriers — the gpu-scope
// barrier of batch A propagates while the CTA computes batch B's chunk
// (and vice versa), hiding sync latency. 64 CTAs x 1024 thr; each CTA
// owns 4 CTA-local packed-ELL slices (K/KT for A and B, 128 rows each;
// cutoff K>=1e-17, ~2% density). Single-poller barrier + syncthreads.
// Multiplicative updates (no log/exp in loop). Deterministic reductions.

#define BB 8
#define NN 2048
#define RSTRIDE 256              // padded max nnz per row (avg ~41)
#define D2CUT 0.391510f          // ln(1e17)/100  -> K >= 1e-17
#define TPB 1024
#define NCTA 64                  // 16 CTAs per batch, 2 batches per CTA
#define NIT 50

__device__ unsigned g_pk[(size_t)NCTA * 4 * 128 * RSTRIDE];   // 4 slices/CTA (33.5 MB)
__device__ float    g_expu[BB * NN], g_expv[BB * NN];
__device__ float    g_part[BB * 16];
__device__ unsigned g_bar[BB];    // zero at load; self-reset each call

__device__ __forceinline__ void bar_arrive(unsigned* p) {
    asm volatile("red.release.gpu.add.u32 [%0], 1;" :: "l"(p) : "memory");
}
__device__ __forceinline__ unsigned bar_peek(unsigned* p) {
    unsigned v;
    asm volatile("ld.acquire.gpu.u32 %0, [%1];" : "=r"(v) : "l"(p) : "memory");
    return v;
}

// ---------------------------------------------------------------------------
__global__ __launch_bounds__(TPB, 1)
void fused_sinkhorn(const float* __restrict__ x1, const float* __restrict__ x2,
                    float* __restrict__ out, float M) {
    __shared__ __align__(16) float pool[NN * 3];   // build pts; then sevA|sevB
    __shared__ unsigned char sit[4][128];          // per-slice per-row iter counts
    __shared__ float red[32];

    int cta = blockIdx.x, crank = cta & 15;
    int bA = cta >> 4, bB = bA + 4;
    int t = threadIdx.x, warp = t >> 5, lane = t & 31;
    const float eps = 1e-8f;

    // ===== build 4 CTA-local ELL slices: sl = 2*pb + m (m=0:K, m=1:KT) =====
    #pragma unroll 1
    for (int sl = 0; sl < 4; ++sl) {
        int bat = (sl < 2) ? bA : bB;
        int m   = sl & 1;
        const float* rowpts = m ? x2 : x1;
        const float* colpts = m ? x1 : x2;
        const float* cp = colpts + (size_t)bat * NN * 3;
        for (int i = t; i < NN * 3; i += TPB) pool[i] = cp[i];
        __syncthreads();

        #pragma unroll 1
        for (int rr = 0; rr < 4; ++rr) {           // 4 rows per warp
            int r = warp * 4 + rr;
            const float* ap = rowpts + ((size_t)bat * NN + crank * 128 + r) * 3;
            float ax = ap[0], ay = ap[1], az = ap[2];
            unsigned* krow = g_pk + ((size_t)(cta * 4 + sl) * 128 + r) * RSTRIDE;

            unsigned base = 0;
            for (int c0 = 0; c0 < NN; c0 += 32) {
                int c = c0 + lane;
                float dx = ax - pool[3 * c];
                float dy = ay - pool[3 * c + 1];
                float dz = az - pool[3 * c + 2];
                float d2 = fmaf(dx, dx, fmaf(dy, dy, dz * dz));
                bool p = d2 < D2CUT;
                unsigned mk = __ballot_sync(0xffffffffu, p);
                if (p) {
                    unsigned idx = base + __popc(mk & ((1u << lane) - 1u));
                    if (idx < RSTRIDE)    // RN-rounded 21-bit val | 11-bit col
                        krow[idx] = ((__float_as_uint(__expf(-100.0f * d2)) + 0x400u)
                                     & 0xFFFFF800u) | (unsigned)c;
                }
                base += __popc(mk);
            }
            unsigned nnz = (base < RSTRIDE) ? base : RSTRIDE;
            unsigned pad = (nnz + 31u) & ~31u;     // 32 entries per group-iter
            for (unsigned idx = nnz + lane; idx < pad; idx += 32) krow[idx] = 0u;
            if (lane == 0) sit[sl][r] = (unsigned char)(pad >> 5);
        }
        __syncthreads();
    }

    // ===== main loop: 100 half-iterations, A/B interleaved barriers =====
    int g = t >> 3, gl = t & 7;                    // 128 groups x 8 lanes
    float* sevA = pool;
    float* sevB = pool + NN;
    int it0 = sit[0][g], it1 = sit[1][g], it2 = sit[2][g], it3 = sit[3][g];
    const uint4* ep0 = (const uint4*)(g_pk + ((size_t)(cta * 4 + 0) * 128 + g) * RSTRIDE) + gl;
    const uint4* ep1 = (const uint4*)(g_pk + ((size_t)(cta * 4 + 1) * 128 + g) * RSTRIDE) + gl;
    const uint4* ep2 = (const uint4*)(g_pk + ((size_t)(cta * 4 + 2) * 128 + g) * RSTRIDE) + gl;
    const uint4* ep3 = (const uint4*)(g_pk + ((size_t)(cta * 4 + 3) * 128 + g) * RSTRIDE) + gl;

    unsigned tgtA = 0, tgtB = 0;

    #pragma unroll 1
    for (int half = 0; half < 100; ++half) {
        int m = half & 1;    // 0: u update (K, reads expv); 1: v update (KT, reads expu)

        #pragma unroll
        for (int pb = 0; pb < 2; ++pb) {
            int bat = pb ? bB : bA;
            float* sev = pb ? sevB : sevA;
            unsigned* barp = &g_bar[bat];
            unsigned tgt = pb ? tgtB : tgtA;

            // wait for previous half of THIS batch (hidden by other batch's chunk)
            if (half > 0) {
                if (t == 0) { while (bar_peek(barp) < tgt) { } }
                __syncthreads();
            }
            // stage source exp-vector
            if (t < NN / 4) {
                ((float4*)sev)[t] = (half == 0)
                    ? make_float4(1.f, 1.f, 1.f, 1.f)
                    : __ldcg((const float4*)((m ? g_expu : g_expv) + bat * NN) + t);
            }
            __syncthreads();

            int sl = pb * 2 + m;
            int iters = (sl == 0) ? it0 : (sl == 1) ? it1 : (sl == 2) ? it2 : it3;
            const uint4* ep = (sl == 0) ? ep0 : (sl == 1) ? ep1 : (sl == 2) ? ep2 : ep3;

            float acc = 0.0f;
            #pragma unroll 2
            for (int i = 0; i < iters; ++i) {
                uint4 e = ep[(size_t)i * 8];
                acc += __uint_as_float(e.x & 0xFFFFF800u) * sev[e.x & 0x7FFu]
                     + __uint_as_float(e.y & 0xFFFFF800u) * sev[e.y & 0x7FFu]
                     + __uint_as_float(e.z & 0xFFFFF800u) * sev[e.z & 0x7FFu]
                     + __uint_as_float(e.w & 0xFFFFF800u) * sev[e.w & 0x7FFu];
            }
            acc += __shfl_xor_sync(0xffffffffu, acc, 4);
            acc += __shfl_xor_sync(0xffffffffu, acc, 2);
            acc += __shfl_xor_sync(0xffffffffu, acc, 1);

            if (gl == 0) {   // multiplicative update: exp(new) = M / (sum + eps)
                float ev = __fdividef(M, acc + eps);
                __stcg((m ? g_expv : g_expu) + bat * NN + crank * 128 + g, ev);
            }
            __syncthreads();                 // all stores done before arrive
            if (t == 0) bar_arrive(barp);
            if (pb) tgtB += 16; else tgtA += 16;
        }
    }

    // ===== epilogue: emd_b = -(1/100) sum_ij k ln(k) e^{u_i} e^{v_j} =====
    #pragma unroll 1
    for (int pb = 0; pb < 2; ++pb) {
        int bat = pb ? bB : bA;
        float* sev = pb ? sevB : sevA;
        unsigned* barp = &g_bar[bat];
        unsigned tgt = pb ? tgtB : tgtA;

        if (t == 0) { while (bar_peek(barp) < tgt) { } }
        __syncthreads();
        if (t < NN / 4)
            ((float4*)sev)[t] = __ldcg((const float4*)(g_expv + bat * NN) + t);
        __syncthreads();

        int iters = pb ? it2 : it0;
        const uint4* ep = pb ? ep2 : ep0;
        float eu = __ldcg(g_expu + bat * NN + crank * 128 + g);

        float racc = 0.0f;
        #pragma unroll 2
        for (int i = 0; i < iters; ++i) {
            uint4 e = ep[(size_t)i * 8];
            unsigned b;
            b = e.x & 0xFFFFF800u;
            if (b) { float k = __uint_as_float(b); racc += k * __logf(k) * sev[e.x & 0x7FFu]; }
            b = e.y & 0xFFFFF800u;
            if (b) { float k = __uint_as_float(b); racc += k * __logf(k) * sev[e.y & 0x7FFu]; }
            b = e.z & 0xFFFFF800u;
            if (b) { float k = __uint_as_float(b); racc += k * __logf(k) * sev[e.z & 0x7FFu]; }
            b = e.w & 0xFFFFF800u;
            if (b) { float k = __uint_as_float(b); racc += k * __logf(k) * sev[e.w & 0x7FFu]; }
        }
        racc += __shfl_xor_sync(0xffffffffu, racc, 4);
        racc += __shfl_xor_sync(0xffffffffu, racc, 2);
        racc += __shfl_xor_sync(0xffffffffu, racc, 1);

        float acc = (gl == 0) ? racc * eu : 0.0f;
        #pragma unroll
        for (int o = 16; o; o >>= 1) acc += __shfl_down_sync(0xffffffffu, acc, o);
        if (lane == 0) red[warp] = acc;
        __syncthreads();
        if (warp == 0) {
            float s = red[lane];
            #pragma unroll
            for (int o = 16; o; o >>= 1) s += __shfl_down_sync(0xffffffffu, s, o);
            if (lane == 0) __stcg(&g_part[bat * 16 + crank], s);
        }
        __syncthreads();
        if (t == 0) bar_arrive(barp);
        if (pb) tgtB += 16; else tgtA += 16;
    }

    // designated CTA (crank 0) finalizes both of its batches
    if (crank == 0 && t == 0) {
        #pragma unroll
        for (int pb = 0; pb < 2; ++pb) {
            int bat = pb ? bB : bA;
            unsigned tgt = pb ? tgtB : tgtA;
            unsigned* barp = &g_bar[bat];
            while (bar_peek(barp) < tgt) { }
            float s = 0.0f;
            #pragma unroll
            for (int k = 0; k < 16; ++k) s += __ldcg(&g_part[bat * 16 + k]);
            out[bat] = -s * 0.01f;       // cost = -ln(K)/100
            *barp = 0u;                  // reset for next graph replay
        }
    }
}

// ---------------------------------------------------------------------------
extern "C" void kernel_launch(void* const* d_in, const int* in_sizes, int n_in,
                              void* d_out, int out_size) {
    (void)in_sizes; (void)n_in; (void)out_size;
    const float* x1 = (const float*)d_in[0];
    const float* x2 = (const float*)d_in[1];
    float* out = (float*)d_out;

    const float M = 1.0f / 2048.0f + 1e-8f;   // exp(log(1/N + eps_log))
    fused_sinkhorn<<<NCTA, TPB>>>(x1, x2, out, M);
}

// round 11
// speedup vs baseline: 1.9539x; 1.9539x over previous
#include <cuda_runtime.h>
#include <math.h>

// Sinkhorn approximate EMD: B=8, N=2048, 3D points, 50 iterations.
// R11: R6 skeleton (fused persistent kernel, 128 CTAs x 1024 thr, 16 CTAs
// per batch, 2 gpu-scope barriers per iteration, single poller) with:
//  - cutoff K >= 1e-17 (~2% density, 41 nnz/row avg; rel_err ~5e-7 validated)
//  - register PREFETCH of next half's first 64 ELL entries across the barrier
//  - multiplicative updates exp(u) = M/(rowsum+eps)  (no log/exp in loop)
//  - leader keeps final exp(u) in a register for the epilogue.

#define BB 8
#define NN 2048
#define NROWS (BB * NN)          // 16384
#define RSTRIDE 256              // padded max nnz per row (avg ~41, max ~150)
#define D2CUT 0.391510f          // ln(1e17)/100  -> K >= 1e-17
#define CPB 16                   // CTAs per batch
#define RPC 128                  // rows per CTA
#define TPB 1024                 // 128 groups x 8 lanes

__device__ unsigned g_pk[2][(size_t)NROWS * RSTRIDE];   // packed K / K^T (33.5 MB)
__device__ float    g_expu[NROWS], g_expv[NROWS];
__device__ float    g_part[BB * CPB];
__device__ unsigned g_bar[BB];   // zero at load; self-reset each call

__device__ __forceinline__ void bar_arrive(unsigned* p) {
    asm volatile("red.release.gpu.add.u32 [%0], 1;" :: "l"(p) : "memory");
}
__device__ __forceinline__ unsigned bar_peek(unsigned* p) {
    unsigned v;
    asm volatile("ld.acquire.gpu.u32 %0, [%1];" : "=r"(v) : "l"(p) : "memory");
    return v;
}

__device__ __forceinline__ float dot4(uint4 e, const float* sev) {
    return __uint_as_float(e.x & 0xFFFFF800u) * sev[e.x & 0x7FFu]
         + __uint_as_float(e.y & 0xFFFFF800u) * sev[e.y & 0x7FFu]
         + __uint_as_float(e.z & 0xFFFFF800u) * sev[e.z & 0x7FFu]
         + __uint_as_float(e.w & 0xFFFFF800u) * sev[e.w & 0x7FFu];
}

// ---------------------------------------------------------------------------
__global__ __launch_bounds__(TPB, 1)
void fused_sinkhorn(const float* __restrict__ x1, const float* __restrict__ x2,
                    float* __restrict__ out, float M) {
    __shared__ float sxbuf[NN * 3];          // build staging; first 2048 reused as sev
    __shared__ unsigned char sit[2][RPC];    // per-row 32-entry iteration counts
    __shared__ float red[32];
    float* sev = sxbuf;

    int cta = blockIdx.x, batch = cta >> 4, crank = cta & (CPB - 1);
    int t = threadIdx.x, warp = t >> 5, lane = t & 31;
    int rowbase = batch * NN + crank * RPC;
    unsigned* barp = &g_bar[batch];
    unsigned target = 0;
    const float eps = 1e-8f;

    // ===== inline build: CTA-private packed-ELL rows of K and K^T =====
    #pragma unroll 1
    for (int m = 0; m < 2; ++m) {
        const float* rowpts = m ? x2 : x1;
        const float* colpts = m ? x1 : x2;
        const float* cp = colpts + (size_t)batch * NN * 3;
        for (int i = t; i < NN * 3; i += TPB) sxbuf[i] = cp[i];
        __syncthreads();

        #pragma unroll 1
        for (int rr = 0; rr < 4; ++rr) {             // 4 rows per warp (32 warps)
            int r   = warp * 4 + rr;
            int row = rowbase + r;
            const float* ap = rowpts + (size_t)row * 3;
            float ax = ap[0], ay = ap[1], az = ap[2];
            unsigned* krow = g_pk[m] + (size_t)row * RSTRIDE;

            unsigned base = 0;
            for (int c0 = 0; c0 < NN; c0 += 32) {
                int c = c0 + lane;
                float dx = ax - sxbuf[3 * c];
                float dy = ay - sxbuf[3 * c + 1];
                float dz = az - sxbuf[3 * c + 2];
                float d2 = fmaf(dx, dx, fmaf(dy, dy, dz * dz));
                bool p = d2 < D2CUT;
                unsigned mk = __ballot_sync(0xffffffffu, p);
                if (p) {
                    unsigned idx = base + __popc(mk & ((1u << lane) - 1u));
                    if (idx < RSTRIDE)   // RN-rounded 21-bit val | 11-bit col
                        krow[idx] = ((__float_as_uint(__expf(-100.0f * d2)) + 0x400u)
                                     & 0xFFFFF800u) | (unsigned)c;
                }
                base += __popc(mk);
            }
            unsigned nnz = (base < RSTRIDE) ? base : RSTRIDE;
            unsigned pad = (nnz + 31u) & ~31u;       // 32 entries per group-iter
            for (unsigned idx = nnz + lane; idx < pad; idx += 32) krow[idx] = 0u;
            if (lane == 0) sit[m][r] = (unsigned char)(pad >> 5);
        }
        __syncthreads();
    }

    // ===== 100 Sinkhorn half-iterations =====
    int g = t >> 3, gl = t & 7;                      // 128 groups x 8 lanes
    int myrow = rowbase + g;
    int itc0 = sit[0][g], itc1 = sit[1][g];
    const uint4* ep0 = (const uint4*)(g_pk[0] + (size_t)myrow * RSTRIDE) + gl;
    const uint4* ep1 = (const uint4*)(g_pk[1] + (size_t)myrow * RSTRIDE) + gl;
    float myeu = 0.0f;                               // leader: final exp(u)

    // prefetch half 0 (m=0, uses ep0); always in-bounds (RSTRIDE=256 -> 8 uint4/lane)
    uint4 f0 = ep0[0];
    uint4 f1 = ep0[8];

    #pragma unroll 1
    for (int half = 0; half < 100; ++half) {
        int m = half & 1;   // 0: u update (K, reads expv); 1: v update (K^T, reads expu)

        // stage source exp-vector (512 threads x float4)
        if (t < NN / 4) {
            ((float4*)sev)[t] = (half == 0)
                ? make_float4(1.f, 1.f, 1.f, 1.f)    // exp(v0) = 1
                : __ldcg((const float4*)((m ? g_expu : g_expv) + batch * NN) + t);
        }
        __syncthreads();

        int iters = m ? itc1 : itc0;
        const uint4* ep = m ? ep1 : ep0;

        float acc = dot4(f0, sev);                   // prefetched chunk 0
        if (iters > 1) acc += dot4(f1, sev);         // prefetched chunk 1
        #pragma unroll 1
        for (int i = 2; i < iters; ++i)              // rare tail (nnz > 64)
            acc += dot4(ep[(size_t)i * 8], sev);

        acc += __shfl_xor_sync(0xffffffffu, acc, 4);
        acc += __shfl_xor_sync(0xffffffffu, acc, 2);
        acc += __shfl_xor_sync(0xffffffffu, acc, 1);

        if (gl == 0) {       // multiplicative update: exp(new) = M / (sum + eps)
            float ev = __fdividef(M, acc + eps);
            if (m == 0) myeu = ev;                   // half 98 leaves final exp(u)
            __stcg((m ? g_expv : g_expu) + myrow, ev);
        }

        // prefetch NEXT half's first 64 entries (matrix is constant — no dependency)
        {
            const uint4* nep = m ? ep0 : ep1;        // next half flips m
            f0 = nep[0];
            f1 = nep[8];
        }
        __syncthreads();                             // all stores issued before arrive

        target += CPB;
        if (t == 0) {
            bar_arrive(barp);
            while (bar_peek(barp) < target) { }      // single poller
        }
        __syncthreads();
    }

    // ===== epilogue: emd_b = -(1/100) sum_ij k ln(k) e^{u_i} e^{v_j} =====
    if (t < NN / 4)
        ((float4*)sev)[t] = __ldcg((const float4*)(g_expv + batch * NN) + t);
    __syncthreads();

    float racc = 0.0f;
    #pragma unroll 1
    for (int i = 0; i < itc0; ++i) {
        uint4 e = ep0[(size_t)i * 8];
        unsigned b;
        b = e.x & 0xFFFFF800u;
        if (b) { float k = __uint_as_float(b); racc += k * __logf(k) * sev[e.x & 0x7FFu]; }
        b = e.y & 0xFFFFF800u;
        if (b) { float k = __uint_as_float(b); racc += k * __logf(k) * sev[e.y & 0x7FFu]; }
        b = e.z & 0xFFFFF800u;
        if (b) { float k = __uint_as_float(b); racc += k * __logf(k) * sev[e.z & 0x7FFu]; }
        b = e.w & 0xFFFFF800u;
        if (b) { float k = __uint_as_float(b); racc += k * __logf(k) * sev[e.w & 0x7FFu]; }
    }
    racc += __shfl_xor_sync(0xffffffffu, racc, 4);
    racc += __shfl_xor_sync(0xffffffffu, racc, 2);
    racc += __shfl_xor_sync(0xffffffffu, racc, 1);

    float acc = (gl == 0) ? racc * myeu : 0.0f;      // leaders carry row sums
    #pragma unroll
    for (int o = 16; o; o >>= 1) acc += __shfl_down_sync(0xffffffffu, acc, o);
    if (lane == 0) red[warp] = acc;
    __syncthreads();
    if (warp == 0) {
        float s = red[lane];
        #pragma unroll
        for (int o = 16; o; o >>= 1) s += __shfl_down_sync(0xffffffffu, s, o);
        if (lane == 0) __stcg(&g_part[cta], s);
    }
    __syncthreads();

    target += CPB;
    if (t == 0) {
        bar_arrive(barp);                 // release covers t0's g_part store
        if (crank == 0) {                 // only rank 0 waits; others exit
            while (bar_peek(barp) < target) { }
            float s = 0.0f;
            #pragma unroll
            for (int k = 0; k < CPB; ++k) s += __ldcg(&g_part[batch * CPB + k]);
            out[batch] = -s * 0.01f;      // cost = -ln(K)/100
            *barp = 0u;                   // reset for next graph replay
        }
    }
}

// ---------------------------------------------------------------------------
extern "C" void kernel_launch(void* const* d_in, const int* in_sizes, int n_in,
                              void* d_out, int out_size) {
    (void)in_sizes; (void)n_in; (void)out_size;
    const float* x1 = (const float*)d_in[0];
    const float* x2 = (const float*)d_in[1];
    float* out = (float*)d_out;

    const float M = 1.0f / 2048.0f + 1e-8f;   // exp(log(1/N + eps_log))
    fused_sinkhorn<<<BB * CPB, TPB>>>(x1, x2, out, M);
}